// round 5
// baseline (speedup 1.0000x reference)
#include <cuda_runtime.h>
#include <cuda_bf16.h>
#include <stdint.h>

#define S_ 4096
#define DM 512
#define HB 16
#define CTX_ELEMS ((size_t)2*S_*DM)
#define QKV ((size_t)HB*S_*64)

// projected q/k/v split into bf16 hi/lo, layout [hb][s][d]
__device__ __nv_bfloat16 g_qh[QKV], g_ql[QKV], g_kh[QKV], g_kl[QKV], g_vh[QKV], g_vl[QKV];
__device__ float g_part[(size_t)HB*S_*32];
__device__ float g_inv[(size_t)HB*S_];

static __device__ __forceinline__ uint32_t s2u(const void* p){
    uint32_t a; asm("{ .reg .u64 t; cvta.to.shared.u64 t, %1; cvt.u32.u64 %0, t; }":"=r"(a):"l"(p)); return a;
}
static __device__ __forceinline__ void split1(float x, __nv_bfloat16& h, __nv_bfloat16& l){
    h = __float2bfloat16_rn(x);
    l = __float2bfloat16_rn(x - __bfloat162float(h));
}
static __device__ __forceinline__ uint32_t pack2(__nv_bfloat16 a, __nv_bfloat16 b){
    return (uint32_t)__bfloat16_as_ushort(a) | ((uint32_t)__bfloat16_as_ushort(b)<<16);
}
static __device__ __forceinline__ void split4(float4 v, uint32_t& h0, uint32_t& h1,
                                              uint32_t& l0, uint32_t& l1){
    __nv_bfloat16 a,b,c,d,e,f,g,h;
    split1(v.x,a,e); split1(v.y,b,f); split1(v.z,c,g); split1(v.w,d,h);
    h0 = pack2(a,b); h1 = pack2(c,d); l0 = pack2(e,f); l1 = pack2(g,h);
}
static __device__ __forceinline__ void mma16816(float* c, const uint32_t* a, const uint32_t* b){
    asm volatile("mma.sync.aligned.m16n8k16.row.col.f32.bf16.bf16.f32 "
        "{%0,%1,%2,%3}, {%4,%5,%6,%7}, {%8,%9}, {%0,%1,%2,%3};"
        : "+f"(c[0]), "+f"(c[1]), "+f"(c[2]), "+f"(c[3])
        : "r"(a[0]),"r"(a[1]),"r"(a[2]),"r"(a[3]), "r"(b[0]),"r"(b[1]));
}
static __device__ __forceinline__ void ldm_x4(uint32_t* r, uint32_t a){
    asm volatile("ldmatrix.sync.aligned.m8n8.x4.shared.b16 {%0,%1,%2,%3}, [%4];"
        : "=r"(r[0]),"=r"(r[1]),"=r"(r[2]),"=r"(r[3]) : "r"(a));
}
static __device__ __forceinline__ void ldm_x2(uint32_t* r, uint32_t a){
    asm volatile("ldmatrix.sync.aligned.m8n8.x2.shared.b16 {%0,%1}, [%2];"
        : "=r"(r[0]),"=r"(r[1]) : "r"(a));
}
static __device__ __forceinline__ void ldm_x2t(uint32_t* r, uint32_t a){
    asm volatile("ldmatrix.sync.aligned.m8n8.x2.trans.shared.b16 {%0,%1}, [%2];"
        : "=r"(r[0]),"=r"(r[1]) : "r"(a));
}

// ============================ projections ==================================
// grid (4 ntile, 64 mtile, 3 z), 256 thr. Y = X@W + b, split bf16 -> [hb][s][d]
__global__ __launch_bounds__(256)
void proj_kernel(const float* __restrict__ Xq, const float* __restrict__ Xk,
                 const float* __restrict__ Xv,
                 const float* __restrict__ Wq, const float* __restrict__ Wk,
                 const float* __restrict__ Wv,
                 const float* __restrict__ bq, const float* __restrict__ bk,
                 const float* __restrict__ bv)
{
    extern __shared__ char sm[];
    const int tid = threadIdx.x, lane = tid&31, wid = tid>>5;
    const int z = blockIdx.z;
    const float* X    = (z==0)?Xq:(z==1)?Xk:Xv;
    const float* W    = (z==0)?Wq:(z==1)?Wk:Wv;
    const float* bias = (z==0)?bq:(z==1)?bk:bv;
    uint32_t* GH = (uint32_t*)((z==0)?g_qh:(z==1)?g_kh:g_vh);
    uint32_t* GL = (uint32_t*)((z==0)?g_ql:(z==1)?g_kl:g_vl);

    const int m0 = blockIdx.y*128, n0 = blockIdx.x*128;
    const uint32_t sb = s2u(sm);
    const uint32_t XH=0, XL=10240, WH=20480, WL=29184;   // pitches: X 80B, W 272B
    const int wm = (wid>>2)*64, wn = (wid&3)*32;

    float acc[4][4][4] = {};

    for (int kc = 0; kc < 16; kc++){
        #pragma unroll
        for (int i = 0; i < 4; i++){                     // X tile 128x32 fp32
            int idx = tid + i*256; int r = idx>>3, c4 = (idx&7)*4;
            float4 v = *(const float4*)(X + (size_t)(m0+r)*DM + kc*32 + c4);
            uint32_t h0,h1,l0,l1; split4(v,h0,h1,l0,l1);
            uint32_t o = r*80 + c4*2;
            *(uint32_t*)(sm+XH+o)   = h0; *(uint32_t*)(sm+XH+o+4) = h1;
            *(uint32_t*)(sm+XL+o)   = l0; *(uint32_t*)(sm+XL+o+4) = l1;
        }
        #pragma unroll
        for (int i = 0; i < 4; i++){                     // W tile 32x128 fp32
            int idx = tid + i*256; int r = idx>>5, c4 = (idx&31)*4;
            float4 v = *(const float4*)(W + (size_t)(kc*32+r)*DM + n0 + c4);
            uint32_t h0,h1,l0,l1; split4(v,h0,h1,l0,l1);
            uint32_t o = r*272 + c4*2;
            *(uint32_t*)(sm+WH+o)   = h0; *(uint32_t*)(sm+WH+o+4) = h1;
            *(uint32_t*)(sm+WL+o)   = l0; *(uint32_t*)(sm+WL+o+4) = l1;
        }
        __syncthreads();
        #pragma unroll
        for (int kf = 0; kf < 2; kf++){
            int ko = kf*16;
            uint32_t ah[4][4], al[4][4], bh[4][2], bl[4][2];
            #pragma unroll
            for (int fm = 0; fm < 4; fm++){
                uint32_t ad = sb + XH + (wm+fm*16+(lane&15))*80 + (ko+(lane>>4)*8)*2;
                ldm_x4(ah[fm], ad); ldm_x4(al[fm], ad + (XL-XH));
            }
            #pragma unroll
            for (int fn = 0; fn < 4; fn++){
                uint32_t ad = sb + WH + (ko+(lane&15))*272 + (wn+fn*8)*2;
                ldm_x2t(bh[fn], ad); ldm_x2t(bl[fn], ad + (WL-WH));
            }
            #pragma unroll
            for (int fm = 0; fm < 4; fm++)
                #pragma unroll
                for (int fn = 0; fn < 4; fn++){
                    mma16816(acc[fm][fn], ah[fm], bh[fn]);
                    mma16816(acc[fm][fn], ah[fm], bl[fn]);
                    mma16816(acc[fm][fn], al[fm], bh[fn]);
                }
        }
        __syncthreads();
    }

    const int b = m0 >> 12, s0 = m0 & (S_-1);
    #pragma unroll
    for (int fm = 0; fm < 4; fm++)
        #pragma unroll
        for (int fn = 0; fn < 4; fn++){
            int col = n0 + wn + fn*8 + (lane&3)*2;
            float b0 = bias[col], b1 = bias[col+1];
            int hb = (col>>6)*2 + b, d = col&63;
            int r0 = wm + fm*16 + (lane>>2);
            __nv_bfloat16 h0,l0,h1,l1;
            split1(acc[fm][fn][0]+b0,h0,l0); split1(acc[fm][fn][1]+b1,h1,l1);
            size_t e0 = ((size_t)hb*S_ + s0 + r0)*64 + d;
            GH[e0>>1] = pack2(h0,h1); GL[e0>>1] = pack2(l0,l1);
            split1(acc[fm][fn][2]+b0,h0,l0); split1(acc[fm][fn][3]+b1,h1,l1);
            size_t e1 = ((size_t)hb*S_ + s0 + r0 + 8)*64 + d;
            GH[e1>>1] = pack2(h0,h1); GL[e1>>1] = pack2(l0,l1);
        }
}

// ============================ scores + exp =================================
// grid (32 jt, 32 it, 16 hb), 256 thr. attn = exp(qk/8) raw, + rowsum partials
__global__ __launch_bounds__(256)
void scores_kernel(float* __restrict__ attn)
{
    extern __shared__ char sm[];
    __shared__ float part[128][4];
    const int tid = threadIdx.x, lane = tid&31, wid = tid>>5;
    const int jt = blockIdx.x, i0 = blockIdx.y*128, hb = blockIdx.z;
    const int j0 = jt*128;
    const uint32_t sb = s2u(sm);
    const uint32_t QH=0, QL=18432, KH=36864, KL=55296;   // pitch 144B

    const uint4* q4h = (const uint4*)g_qh; const uint4* q4l = (const uint4*)g_ql;
    const uint4* k4h = (const uint4*)g_kh; const uint4* k4l = (const uint4*)g_kl;
    #pragma unroll
    for (int i = 0; i < 4; i++){
        int idx = tid + i*256; int r = idx>>3, ch = idx&7;
        uint32_t o = r*144 + ch*16;
        *(uint4*)(sm+QH+o) = q4h[((size_t)hb*S_ + i0 + r)*8 + ch];
        *(uint4*)(sm+QL+o) = q4l[((size_t)hb*S_ + i0 + r)*8 + ch];
        *(uint4*)(sm+KH+o) = k4h[((size_t)hb*S_ + j0 + r)*8 + ch];
        *(uint4*)(sm+KL+o) = k4l[((size_t)hb*S_ + j0 + r)*8 + ch];
    }
    __syncthreads();

    const int wm = (wid>>2)*64, wn = (wid&3)*32;
    float acc[4][4][4] = {};
    #pragma unroll
    for (int kf = 0; kf < 4; kf++){
        int ko = kf*16;
        uint32_t ah[4][4], al[4][4], bh[4][2], bl[4][2];
        #pragma unroll
        for (int fm = 0; fm < 4; fm++){
            uint32_t ad = sb + QH + (wm+fm*16+(lane&15))*144 + (ko+(lane>>4)*8)*2;
            ldm_x4(ah[fm], ad); ldm_x4(al[fm], ad + (QL-QH));
        }
        #pragma unroll
        for (int fn = 0; fn < 4; fn++){
            uint32_t ad = sb + KH + (wn+fn*8+(lane&7))*144 + (ko+((lane>>3)&1)*8)*2;
            ldm_x2(bh[fn], ad); ldm_x2(bl[fn], ad + (KL-KH));
        }
        #pragma unroll
        for (int fm = 0; fm < 4; fm++)
            #pragma unroll
            for (int fn = 0; fn < 4; fn++){
                mma16816(acc[fm][fn], ah[fm], bh[fn]);
                mma16816(acc[fm][fn], ah[fm], bl[fn]);
                mma16816(acc[fm][fn], al[fm], bh[fn]);
            }
    }

    const float C = 0.18033688011112042f;   // log2(e)/8
    #pragma unroll
    for (int fm = 0; fm < 4; fm++){
        int r0 = wm + fm*16 + (lane>>2);
        float rs0 = 0.f, rs1 = 0.f;
        #pragma unroll
        for (int fn = 0; fn < 4; fn++){
            int col = wn + fn*8 + (lane&3)*2;
            float e0 = exp2f(acc[fm][fn][0]*C), e1 = exp2f(acc[fm][fn][1]*C);
            float e2 = exp2f(acc[fm][fn][2]*C), e3 = exp2f(acc[fm][fn][3]*C);
            rs0 += e0 + e1; rs1 += e2 + e3;
            float2* p0 = (float2*)(attn + ((size_t)hb*S_ + i0 + r0)*S_ + j0 + col);
            float2* p1 = (float2*)(attn + ((size_t)hb*S_ + i0 + r0 + 8)*S_ + j0 + col);
            *p0 = make_float2(e0,e1); *p1 = make_float2(e2,e3);
        }
        rs0 += __shfl_xor_sync(0xffffffffu, rs0, 1); rs0 += __shfl_xor_sync(0xffffffffu, rs0, 2);
        rs1 += __shfl_xor_sync(0xffffffffu, rs1, 1); rs1 += __shfl_xor_sync(0xffffffffu, rs1, 2);
        if ((lane&3) == 0){ part[r0][wid&3] = rs0; part[r0+8][wid&3] = rs1; }
    }
    __syncthreads();
    if (tid < 128)
        g_part[((size_t)hb*S_ + i0 + tid)*32 + jt] =
            part[tid][0] + part[tid][1] + part[tid][2] + part[tid][3];
}

// ============================ rowsum reduce ================================
__global__ __launch_bounds__(256)
void reduce_kernel()
{
    int r = blockIdx.x*256 + threadIdx.x;
    const float4* p = (const float4*)(g_part + (size_t)r*32);
    float s = 0.f;
    #pragma unroll
    for (int i = 0; i < 8; i++){ float4 v = p[i]; s += v.x+v.y+v.z+v.w; }
    g_inv[r] = 1.0f / s;
}

// ============================ context (+ normalize attn) ===================
// grid (32 it, 16 hb), 256 thr. Normalizes attn in place; ctx = (E@V)*inv.
__global__ __launch_bounds__(256)
void context_kernel(float* __restrict__ attn, float* __restrict__ ctx)
{
    extern __shared__ char sm[];
    __shared__ float s_inv[128];
    const int tid = threadIdx.x, lane = tid&31, wid = tid>>5;
    const int i0 = blockIdx.x*128, hb = blockIdx.y;
    const int h = hb>>1, b = hb&1;
    const uint32_t sb = s2u(sm);
    const uint32_t PH=0, PL=18432, VH=36864, VL=46080;   // pitch 144B

    if (tid < 128) s_inv[tid] = g_inv[(size_t)hb*S_ + i0 + tid];
    __syncthreads();

    const int wm = (wid>>1)*32, wn = (wid&1)*32;
    float acc[2][4][4] = {};
    const uint4* v4h = (const uint4*)g_vh; const uint4* v4l = (const uint4*)g_vl;

    for (int jc = 0; jc < 64; jc++){
        const int row = tid>>1, cb = (tid&1)*32;
        float* prow = attn + ((size_t)hb*S_ + i0 + row)*S_ + jc*64 + cb;
        const float iv = s_inv[row];
        #pragma unroll
        for (int q = 0; q < 8; q++){
            float4 v = *(float4*)(prow + q*4);
            float4 nv = make_float4(v.x*iv, v.y*iv, v.z*iv, v.w*iv);
            *(float4*)(prow + q*4) = nv;                 // normalized attn output
            uint32_t h0,h1,l0,l1; split4(v,h0,h1,l0,l1); // raw E for MMA
            uint32_t o = row*144 + (cb + q*4)*2;
            *(uint32_t*)(sm+PH+o)   = h0; *(uint32_t*)(sm+PH+o+4) = h1;
            *(uint32_t*)(sm+PL+o)   = l0; *(uint32_t*)(sm+PL+o+4) = l1;
        }
        #pragma unroll
        for (int i = 0; i < 2; i++){
            int idx = tid + i*256; int r = idx>>3, ch = idx&7;
            uint32_t o = r*144 + ch*16;
            *(uint4*)(sm+VH+o) = v4h[((size_t)hb*S_ + jc*64 + r)*8 + ch];
            *(uint4*)(sm+VL+o) = v4l[((size_t)hb*S_ + jc*64 + r)*8 + ch];
        }
        __syncthreads();
        #pragma unroll
        for (int kf = 0; kf < 4; kf++){
            int ko = kf*16;
            uint32_t ah[2][4], al[2][4], bh[4][2], bl[4][2];
            #pragma unroll
            for (int fm = 0; fm < 2; fm++){
                uint32_t ad = sb + PH + (wm+fm*16+(lane&15))*144 + (ko+(lane>>4)*8)*2;
                ldm_x4(ah[fm], ad); ldm_x4(al[fm], ad + (PL-PH));
            }
            #pragma unroll
            for (int fn = 0; fn < 4; fn++){
                uint32_t ad = sb + VH + (ko+(lane&15))*144 + (wn+fn*8)*2;
                ldm_x2t(bh[fn], ad); ldm_x2t(bl[fn], ad + (VL-VH));
            }
            #pragma unroll
            for (int fm = 0; fm < 2; fm++)
                #pragma unroll
                for (int fn = 0; fn < 4; fn++){
                    mma16816(acc[fm][fn], ah[fm], bh[fn]);
                    mma16816(acc[fm][fn], ah[fm], bl[fn]);
                    mma16816(acc[fm][fn], al[fm], bh[fn]);
                }
        }
        __syncthreads();
    }

    #pragma unroll
    for (int fm = 0; fm < 2; fm++)
        #pragma unroll
        for (int fn = 0; fn < 4; fn++){
            int r0 = wm + fm*16 + (lane>>2), r1 = r0 + 8;
            int col = wn + fn*8 + (lane&3)*2;
            float iv0 = s_inv[r0], iv1 = s_inv[r1];
            float2* o0 = (float2*)(ctx + ((size_t)b*S_ + i0 + r0)*DM + h*64 + col);
            float2* o1 = (float2*)(ctx + ((size_t)b*S_ + i0 + r1)*DM + h*64 + col);
            *o0 = make_float2(acc[fm][fn][0]*iv0, acc[fm][fn][1]*iv0);
            *o1 = make_float2(acc[fm][fn][2]*iv1, acc[fm][fn][3]*iv1);
        }
}

// ===========================================================================
extern "C" void kernel_launch(void* const* d_in, const int* in_sizes, int n_in,
                              void* d_out, int out_size)
{
    const float* query = (const float*)d_in[0];
    const float* key   = (const float*)d_in[1];
    const float* value = (const float*)d_in[2];
    const float* Wq    = (const float*)d_in[3];
    const float* bq    = (const float*)d_in[4];
    const float* Wk    = (const float*)d_in[5];
    const float* bk    = (const float*)d_in[6];
    const float* Wv    = (const float*)d_in[7];
    const float* bv    = (const float*)d_in[8];

    float* ctx  = (float*)d_out;
    float* attn = (float*)d_out + CTX_ELEMS;

    cudaFuncSetAttribute(scores_kernel,  cudaFuncAttributeMaxDynamicSharedMemorySize, 73728);
    cudaFuncSetAttribute(context_kernel, cudaFuncAttributeMaxDynamicSharedMemorySize, 55296);

    proj_kernel<<<dim3(4,64,3), 256, 37888>>>(query, key, value, Wq, Wk, Wv, bq, bk, bv);
    scores_kernel<<<dim3(32,32,16), 256, 73728>>>(attn);
    reduce_kernel<<<256, 256>>>();
    context_kernel<<<dim3(32,16), 256, 55296>>>(attn, ctx);
}